// round 16
// baseline (speedup 1.0000x reference)
#include <cuda_runtime.h>
#include <cstdint>
#include <cstddef>
#include <math.h>

#define KN 1024       // N_EMBED (atoms)
#define DD 128        // DIM
#define NN 16384      // number of patches (16*32*32)
#define HW 1024       // 32*32

// output flat offsets (tuple flatten order of the reference return)
#define OFF_QD1    2097152
#define OFF_QD2    2097153
#define OFF_IDS    2097154
#define OFF_NSTEPS 18874370
#define OFF_MEAND  18874371
#define OFF_MEANZ  18874372
#define OFF_NORMZ  18874373
#define OFF_TOPP   18874374
#define OFF_NZEROS 18874375

// ---------------- device scratch (allocation-free rule: __device__ globals) ----------
__device__ __align__(16) float d_Dt[KN * DD];
__device__ __align__(16) float d_G[KN * KN];
__device__ __align__(16) float d_DtX[KN * NN];
__device__ __align__(16) float d_Z[KN * NN];
__device__ __align__(16) float d_Y0[KN * NN];
__device__ __align__(16) float d_Y1[KN * NN];
__device__ float d_v[KN];
__device__ float d_w[KN];
__device__ float d_scal[4];              // [0]=step, [1]=thr
__device__ float d_meanD_part[KN];
__device__ float d_sumabs_part[2048];
__device__ float d_qd_part[128];
__device__ int   d_hist[16];

// ---------------- packed f32x2 helpers (Blackwell base-ISA; NOT tcgen05) ------------
// Lane-wise IEEE fp32 RN fma: bitwise identical to the scalar FFMA chain.
__device__ __forceinline__ unsigned long long pack_ff(float x, float y) {
    unsigned long long d;
    asm("mov.b64 %0, {%1, %2};" : "=l"(d)
        : "r"(__float_as_uint(x)), "r"(__float_as_uint(y)));
    return d;
}
__device__ __forceinline__ void fma_f32x2(unsigned long long& c,
                                          unsigned long long a,
                                          unsigned long long b) {
    asm("fma.rn.f32x2 %0, %1, %2, %3;" : "=l"(c) : "l"(a), "l"(b), "l"(c));
}
__device__ __forceinline__ void unpack_ff(float& x, float& y, unsigned long long d) {
    uint32_t lo, hi;
    asm("mov.b64 {%0, %1}, %2;" : "=r"(lo), "=r"(hi) : "l"(d));
    x = __uint_as_float(lo);
    y = __uint_as_float(hi);
}

// ---------------- tiny init ----------------
__global__ void k_init() {
    if (threadIdx.x < 16) d_hist[threadIdx.x] = 0;
}

// ---------------- normalize dictionary columns; build Dt; per-column |.| sums -------
__global__ void k_normalize(const float* __restrict__ D) {
    int k = blockIdx.x;
    int c = threadIdx.x;
    float v = D[c * KN + k];
    __shared__ float red[128];
    __shared__ float nrm;
    red[c] = v * v;
    __syncthreads();
    for (int s = 64; s; s >>= 1) { if (c < s) red[c] += red[c + s]; __syncthreads(); }
    if (c == 0) nrm = sqrtf(red[0]);
    __syncthreads();
    float o = v / nrm;
    d_Dt[k * DD + c] = o;
    red[c] = fabsf(o);
    __syncthreads();
    for (int s = 64; s; s >>= 1) { if (c < s) red[c] += red[c + s]; __syncthreads(); }
    if (c == 0) d_meanD_part[k] = red[0];
}

// ---------------- Gram matrix G = Dt * Dt^T ----------------------
__global__ __launch_bounds__(256) void k_gram() {
    __shared__ float Ai[32][128];
    __shared__ float Aj[32][128];
    int i0 = blockIdx.y * 32, j0 = blockIdx.x * 32;
    int tid = threadIdx.x;
    #pragma unroll
    for (int l = 0; l < 4; l++) {
        int id = tid + l * 256;
        int r = id >> 5, c4 = id & 31;
        *(float4*)&Ai[r][c4 * 4] = *(const float4*)&d_Dt[(i0 + r) * DD + c4 * 4];
        *(float4*)&Aj[r][c4 * 4] = *(const float4*)&d_Dt[(j0 + r) * DD + c4 * 4];
    }
    __syncthreads();
    int tx = tid & 15, ty = tid >> 4;
    float a00 = 0.f, a01 = 0.f, a10 = 0.f, a11 = 0.f;
    #pragma unroll 4
    for (int c = 0; c < 128; c++) {
        float x0 = Ai[ty * 2 + 0][c], x1 = Ai[ty * 2 + 1][c];
        float y0 = Aj[tx * 2 + 0][c], y1 = Aj[tx * 2 + 1][c];
        a00 += x0 * y0; a01 += x0 * y1; a10 += x1 * y0; a11 += x1 * y1;
    }
    d_G[(i0 + ty * 2 + 0) * KN + j0 + tx * 2 + 0] = a00;
    d_G[(i0 + ty * 2 + 0) * KN + j0 + tx * 2 + 1] = a01;
    d_G[(i0 + ty * 2 + 1) * KN + j0 + tx * 2 + 0] = a10;
    d_G[(i0 + ty * 2 + 1) * KN + j0 + tx * 2 + 1] = a11;
}

// ---------------- power iteration ----------------
__global__ void k_pitinit() {
    for (int i = threadIdx.x; i < KN; i += blockDim.x) d_v[i] = 0.03125f;
}
__global__ void k_matvec() {
    int row = blockIdx.x;
    int t = threadIdx.x;
    const float* g = &d_G[row * KN];
    float s = 0.f;
    for (int j = t; j < KN; j += 128) s += g[j] * d_v[j];
    __shared__ float red[128];
    red[t] = s; __syncthreads();
    for (int k2 = 64; k2; k2 >>= 1) { if (t < k2) red[t] += red[t + k2]; __syncthreads(); }
    if (t == 0) d_w[row] = red[0];
}
__global__ void k_pitnorm() {
    int t = threadIdx.x;
    float s = 0.f;
    for (int i = t; i < KN; i += 256) { float w = d_w[i]; s += w * w; }
    __shared__ float red[256];
    __shared__ float nrm;
    red[t] = s; __syncthreads();
    for (int k2 = 128; k2; k2 >>= 1) { if (t < k2) red[t] += red[t + k2]; __syncthreads(); }
    if (t == 0) nrm = sqrtf(red[0]) + 1e-12f;
    __syncthreads();
    for (int i = t; i < KN; i += 256) d_v[i] = d_w[i] / nrm;
}
__global__ void k_pitfinal() {
    int t = threadIdx.x;
    float s = 0.f;
    for (int i = t; i < KN; i += 256) s += d_v[i] * d_w[i];
    __shared__ float red[256];
    red[t] = s; __syncthreads();
    for (int k2 = 128; k2; k2 >>= 1) { if (t < k2) red[t] += red[t + k2]; __syncthreads(); }
    if (t == 0) {
        float step = 1.0f / red[0];
        d_scal[0] = step;
        d_scal[1] = 0.1f * step;
    }
}

// ---------------- DtX = Dt (1024x128) @ X (128x16384) ------------------------------
__global__ __launch_bounds__(256) void k_dtx(const float* __restrict__ X) {
    __shared__ float As[16][128];
    __shared__ float Bs[16][128];
    int tid = threadIdx.x;
    int k0 = blockIdx.x * 128;
    int n0 = blockIdx.y * 128;
    int b = n0 >> 10, hw0 = n0 & 1023;
    const float* Xb = X + b * (DD * HW) + hw0;
    int tx = tid & 15, ty = tid >> 4;
    float acc[8][8];
    #pragma unroll
    for (int i = 0; i < 8; i++)
        #pragma unroll
        for (int j = 0; j < 8; j++) acc[i][j] = 0.f;
    for (int c0 = 0; c0 < DD; c0 += 16) {
        #pragma unroll
        for (int l = 0; l < 2; l++) {
            int id = tid + l * 256;
            int r = id >> 2, q = id & 3;
            float4 av = *(const float4*)&d_Dt[(k0 + r) * DD + c0 + q * 4];
            As[q * 4 + 0][r] = av.x; As[q * 4 + 1][r] = av.y;
            As[q * 4 + 2][r] = av.z; As[q * 4 + 3][r] = av.w;
            int br = id >> 5, bc = id & 31;
            float4 bv = *(const float4*)&Xb[(c0 + br) * HW + bc * 4];
            *(float4*)&Bs[br][bc * 4] = bv;
        }
        __syncthreads();
        #pragma unroll
        for (int kk = 0; kk < 16; kk++) {
            float a[8], bb[8];
            #pragma unroll
            for (int i = 0; i < 8; i++) a[i] = As[kk][ty * 8 + i];
            #pragma unroll
            for (int j = 0; j < 8; j++) bb[j] = Bs[kk][tx * 8 + j];
            #pragma unroll
            for (int i = 0; i < 8; i++)
                #pragma unroll
                for (int j = 0; j < 8; j++) acc[i][j] += a[i] * bb[j];
        }
        __syncthreads();
    }
    #pragma unroll
    for (int i = 0; i < 8; i++) {
        int k = k0 + ty * 8 + i;
        #pragma unroll
        for (int j = 0; j < 8; j++)
            d_DtX[k * NN + n0 + tx * 8 + j] = acc[i][j];
    }
}

// ---------------- FISTA iteration 1 (y0 = 0) ----------------
__global__ void k_first() {
    float step = d_scal[0], thr = d_scal[1];
    for (int i = blockIdx.x * blockDim.x + threadIdx.x; i < KN * NN; i += gridDim.x * blockDim.x) {
        float v = step * d_DtX[i];
        float a = fabsf(v) - thr;
        float z = (a > 0.f) ? copysignf(a, v) : 0.f;
        d_Z[i] = z;
        d_Y0[i] = z;   // momentum for iter 1 is 0 -> y2 = z1
    }
}

// ---------------- main FISTA GEMM: packed-f32x2 pipelined + fused prox/momentum -----
// fma.rn.f32x2 is lane-wise IEEE fp32 RN -> the per-element fma chain (kk ascending)
// is BITWISE IDENTICAL to the scalar FFMA version that passed at 1.524465e-07.
// 2x fp32 issue throughput (FFMA2 rt=1 FMA-slot per lane-pair vs FFMA-3reg rt=2).
__global__ __launch_bounds__(256, 2) void k_fista(float m, int ping) {
    const float* __restrict__ Yin = ping ? d_Y1 : d_Y0;
    float* __restrict__ Yout      = ping ? d_Y0 : d_Y1;
    __shared__ float As[2][16][128];
    __shared__ float Bs[2][16][128];
    int tid = threadIdx.x;
    int k0 = blockIdx.x * 128;   // x fast: 8 k-tiles share the Y n-tile via L2
    int n0 = blockIdx.y * 128;
    int tx = tid & 15, ty = tid >> 4;
    int ar = tid >> 2, aq = tid & 3;     // A ldg coords (rows ar, ar+64)
    int br = tid >> 5, bc = tid & 31;    // B cp.async coords (rows br, br+8)

    uint32_t bsBase;
    asm("{ .reg .u64 t; cvta.to.shared.u64 t, %1; cvt.u32.u64 %0, t; }"
        : "=r"(bsBase) : "l"(&Bs[0][0][0]));

    unsigned long long acc2[8][4];       // [i][j2]: cols {2*j2, 2*j2+1} of the 8-wide j
    #pragma unroll
    for (int i = 0; i < 8; i++)
        #pragma unroll
        for (int j2 = 0; j2 < 4; j2++) acc2[i][j2] = 0ull;

    // prologue: stage chunk 0
    float4 avA0 = *(const float4*)&d_G[(k0 + ar) * KN + aq * 4];
    float4 avA1 = *(const float4*)&d_G[(k0 + ar + 64) * KN + aq * 4];
    {
        const float* s0 = &Yin[br * NN + n0 + bc * 4];
        const float* s1 = &Yin[(br + 8) * NN + n0 + bc * 4];
        uint32_t d0 = bsBase + (uint32_t)((br * 128 + bc * 4) * 4);
        uint32_t d1 = bsBase + (uint32_t)(((br + 8) * 128 + bc * 4) * 4);
        asm volatile("cp.async.ca.shared.global [%0], [%1], 16;" :: "r"(d0), "l"(s0));
        asm volatile("cp.async.ca.shared.global [%0], [%1], 16;" :: "r"(d1), "l"(s1));
        asm volatile("cp.async.commit_group;" ::: "memory");
    }

    for (int c = 0; c < 64; c++) {
        int cur = c & 1;
        // transpose-store staged A chunk c
        As[cur][aq * 4 + 0][ar] = avA0.x;
        As[cur][aq * 4 + 1][ar] = avA0.y;
        As[cur][aq * 4 + 2][ar] = avA0.z;
        As[cur][aq * 4 + 3][ar] = avA0.w;
        As[cur][aq * 4 + 0][ar + 64] = avA1.x;
        As[cur][aq * 4 + 1][ar + 64] = avA1.y;
        As[cur][aq * 4 + 2][ar + 64] = avA1.z;
        As[cur][aq * 4 + 3][ar + 64] = avA1.w;
        asm volatile("cp.async.wait_group 0;" ::: "memory");
        __syncthreads();

        if (c < 63) {
            int kc = (c + 1) * 16;
            avA0 = *(const float4*)&d_G[(k0 + ar) * KN + kc + aq * 4];
            avA1 = *(const float4*)&d_G[(k0 + ar + 64) * KN + kc + aq * 4];
            int nxt = cur ^ 1;
            const float* s0 = &Yin[(kc + br) * NN + n0 + bc * 4];
            const float* s1 = &Yin[(kc + br + 8) * NN + n0 + bc * 4];
            uint32_t d0 = bsBase + (uint32_t)((nxt * 2048 + br * 128 + bc * 4) * 4);
            uint32_t d1 = bsBase + (uint32_t)((nxt * 2048 + (br + 8) * 128 + bc * 4) * 4);
            asm volatile("cp.async.ca.shared.global [%0], [%1], 16;" :: "r"(d0), "l"(s0));
            asm volatile("cp.async.ca.shared.global [%0], [%1], 16;" :: "r"(d1), "l"(s1));
            asm volatile("cp.async.commit_group;" ::: "memory");
        }

        #pragma unroll
        for (int kk = 0; kk < 16; kk++) {
            unsigned long long b2[4];
            #pragma unroll
            for (int j2 = 0; j2 < 4; j2++)
                b2[j2] = *(const unsigned long long*)&Bs[cur][kk][tx * 8 + j2 * 2];
            #pragma unroll
            for (int i = 0; i < 8; i++) {
                float av = As[cur][kk][ty * 8 + i];
                unsigned long long a2 = pack_ff(av, av);
                #pragma unroll
                for (int j2 = 0; j2 < 4; j2++)
                    fma_f32x2(acc2[i][j2], a2, b2[j2]);
            }
        }
        // no trailing barrier: buffers alternate; the one sync above suffices
    }

    float step = d_scal[0], thr = d_scal[1];
    #pragma unroll
    for (int i = 0; i < 8; i++) {
        int k = k0 + ty * 8 + i;
        #pragma unroll
        for (int j2 = 0; j2 < 4; j2++) {
            float g0, g1;
            unpack_ff(g0, g1, acc2[i][j2]);
            #pragma unroll
            for (int h = 0; h < 2; h++) {
                float g = h ? g1 : g0;
                int n = n0 + tx * 8 + j2 * 2 + h;
                int idx = k * NN + n;
                float yv = Yin[idx];
                float dx = d_DtX[idx];
                float zp = d_Z[idx];
                float v = yv - step * (g - dx);
                float a = fabsf(v) - thr;
                float zn = (a > 0.f) ? copysignf(a, v) : 0.f;
                d_Z[idx] = zn;
                Yout[idx] = zn + m * (zn - zp);
            }
        }
    }
}

// ---------------- top-10 per column + 8-bit quantization + stats --------------------
__global__ __launch_bounds__(256) void k_topk() {
    __shared__ float sm[8 * 1025];
    __shared__ float wsum[8];
    int n0 = blockIdx.x * 8;
    int tid = threadIdx.x;
    for (int idx = tid; idx < 8 * 1024; idx += 256) {
        int k = idx >> 3, c = idx & 7;
        sm[c * 1025 + k] = d_Z[k * NN + n0 + c];
    }
    __syncthreads();
    int warp = tid >> 5, lane = tid & 31;
    float* col = &sm[warp * 1025];
    unsigned mask = 0;
    for (int r = 0; r < 10; r++) {
        float best = -1.0f; int bk = 1 << 30;
        #pragma unroll
        for (int i = 0; i < 32; i++) {
            if (!((mask >> i) & 1u)) {
                float v = fabsf(col[i * 32 + lane]);
                if (v > best) { best = v; bk = i * 32 + lane; }
            }
        }
        #pragma unroll
        for (int off = 16; off; off >>= 1) {
            float ov = __shfl_xor_sync(0xffffffffu, best, off);
            int ok = __shfl_xor_sync(0xffffffffu, bk, off);
            if (ov > best || (ov == best && ok < bk)) { best = ov; bk = ok; }
        }
        if (lane == (bk & 31)) mask |= 1u << (bk >> 5);
    }
    float sa = 0.f; int nz = 0;
    #pragma unroll
    for (int i = 0; i < 32; i++) {
        float z = col[i * 32 + lane];
        float q = 0.f;
        if ((mask >> i) & 1u) {
            float zc = fminf(fmaxf(z, -0.55f), 0.55f);
            float u = (zc - (-0.55f)) / (0.55f - (-0.55f));
            u = rintf(u * 256.0f) * 0.00390625f;
            q = u * (0.55f - (-0.55f)) + (-0.55f);
        }
        col[i * 32 + lane] = q;
        sa += fabsf(q);
        nz += (q != 0.f) ? 1 : 0;
    }
    #pragma unroll
    for (int off = 16; off; off >>= 1) {
        sa += __shfl_xor_sync(0xffffffffu, sa, off);
        nz += __shfl_xor_sync(0xffffffffu, nz, off);
    }
    if (lane == 0) { atomicAdd(&d_hist[nz], 1); wsum[warp] = sa; }
    __syncthreads();
    if (tid == 0) {
        float s = 0.f;
        for (int w = 0; w < 8; w++) s += wsum[w];
        d_sumabs_part[blockIdx.x] = s;
    }
    for (int idx = tid; idx < 8 * 1024; idx += 256) {
        int k = idx >> 3, c = idx & 7;
        d_Z[k * NN + n0 + c] = sm[c * 1025 + k];
    }
}

// ---------------- ids output (out+OFF_IDS only 8B aligned -> float2) ----------------
__global__ void k_ids(float* __restrict__ out) {
    int bk = blockIdx.x;
    int k = bk & 1023, b = bk >> 10;
    const float2* src = (const float2*)&d_Z[k * NN + b * HW];
    float2* dst = (float2*)(out + OFF_IDS + (size_t)b * (KN * HW) + (size_t)k * HW);
    int t = threadIdx.x;
    dst[t] = src[t];
    dst[t + 256] = src[t + 256];
}

// ---------------- reconstruction + straight-through + qd ----------------------------
__global__ __launch_bounds__(256) void k_recon(const float* __restrict__ X, float* __restrict__ out) {
    __shared__ float As[16][128];
    __shared__ float Bs[16][128];
    int tid = threadIdx.x;
    int n0 = blockIdx.x * 128;
    int tx = tid & 15, ty = tid >> 4;
    float acc[8][8];
    #pragma unroll
    for (int i = 0; i < 8; i++)
        #pragma unroll
        for (int j = 0; j < 8; j++) acc[i][j] = 0.f;
    for (int k0 = 0; k0 < KN; k0 += 16) {
        #pragma unroll
        for (int l = 0; l < 2; l++) {
            int id = tid + l * 256;
            int r = id >> 5, c4 = id & 31;
            *(float4*)&As[r][c4 * 4] = *(const float4*)&d_Dt[(k0 + r) * DD + c4 * 4];
            *(float4*)&Bs[r][c4 * 4] = *(const float4*)&d_Z[(k0 + r) * NN + n0 + c4 * 4];
        }
        __syncthreads();
        #pragma unroll
        for (int kk = 0; kk < 16; kk++) {
            float a[8], bb[8];
            #pragma unroll
            for (int i = 0; i < 8; i++) a[i] = As[kk][ty * 8 + i];
            #pragma unroll
            for (int j = 0; j < 8; j++) bb[j] = Bs[kk][tx * 8 + j];
            #pragma unroll
            for (int i = 0; i < 8; i++)
                #pragma unroll
                for (int j = 0; j < 8; j++) acc[i][j] += a[i] * bb[j];
        }
        __syncthreads();
    }
    int b = n0 >> 10, hw0 = n0 & 1023;
    float sq = 0.f;
    #pragma unroll
    for (int i = 0; i < 8; i++) {
        int c = ty * 8 + i;
        #pragma unroll
        for (int j = 0; j < 8; j++) {
            int hw = hw0 + tx * 8 + j;
            int gi = b * (DD * HW) + c * HW + hw;
            float x = X[gi];
            float d = acc[i][j] - x;
            sq += d * d;
            out[gi] = x + d;
        }
    }
    __shared__ float red[256];
    red[tid] = sq; __syncthreads();
    for (int k2 = 128; k2; k2 >>= 1) { if (tid < k2) red[tid] += red[tid + k2]; __syncthreads(); }
    if (tid == 0) d_qd_part[blockIdx.x] = red[0];
}

// ---------------- final scalars ----------------
__global__ void k_scalars(float* __restrict__ out) {
    __shared__ float red[256];
    int t = threadIdx.x;
    float s = (t < 128) ? d_qd_part[t] : 0.f;
    red[t] = s; __syncthreads();
    for (int k2 = 128; k2; k2 >>= 1) { if (t < k2) red[t] += red[t + k2]; __syncthreads(); }
    if (t == 0) { float qd = red[0] / 2097152.0f; out[OFF_QD1] = qd; out[OFF_QD2] = qd; }
    __syncthreads();
    s = 0.f;
    for (int i = t; i < KN; i += 256) s += d_meanD_part[i];
    red[t] = s; __syncthreads();
    for (int k2 = 128; k2; k2 >>= 1) { if (t < k2) red[t] += red[t + k2]; __syncthreads(); }
    if (t == 0) out[OFF_MEAND] = red[0] / 131072.0f;
    __syncthreads();
    s = 0.f;
    for (int i = t; i < 2048; i += 256) s += d_sumabs_part[i];
    red[t] = s; __syncthreads();
    for (int k2 = 128; k2; k2 >>= 1) { if (t < k2) red[t] += red[t + k2]; __syncthreads(); }
    if (t == 0) out[OFF_MEANZ] = red[0] / 16777216.0f;
    if (t == 0) {
        out[OFF_NSTEPS] = 50.0f;
        int cum = 0, perc = 0, found = 0;
        for (int v = 10; v >= 0; v--) {
            cum += d_hist[v];
            if (!found && cum >= 163) { perc = v; found = 1; }
        }
        float sv = 0.f;
        for (int v = 1; v <= 10; v++) sv += (float)v * (float)d_hist[v];
        out[OFF_NORMZ]  = sv / 16384.0f;
        out[OFF_TOPP]   = (float)perc;
        out[OFF_NZEROS] = (float)d_hist[0];
    }
}

// ---------------- host driver ----------------
extern "C" void kernel_launch(void* const* d_in, const int* in_sizes, int n_in,
                              void* d_out, int out_size) {
    (void)n_in; (void)out_size;
    const float* a0 = (const float*)d_in[0];
    const float* a1 = (const float*)d_in[1];
    const float* X; const float* Ddict;
    if (in_sizes[0] == KN * DD) { Ddict = a0; X = a1; }
    else                        { X = a0;     Ddict = a1; }
    float* out = (float*)d_out;

    k_init<<<1, 32>>>();
    k_normalize<<<KN, 128>>>(Ddict);
    k_gram<<<dim3(32, 32), 256>>>();
    k_pitinit<<<1, 256>>>();
    for (int i = 0; i < 20; i++) {
        k_matvec<<<KN, 128>>>();
        k_pitnorm<<<1, 256>>>();
    }
    k_matvec<<<KN, 128>>>();
    k_pitfinal<<<1, 256>>>();

    k_dtx<<<dim3(8, 128), 256>>>(X);
    k_first<<<4096, 256>>>();

    // fp32 Nesterov recurrence, mirroring the JAX op order
    float t = 1.0f;
    {   // iteration 1 (consumed by k_first, momentum 0)
        float tn = (1.0f + sqrtf(1.0f + 4.0f * t * t)) / 2.0f;
        t = tn;
    }
    for (int it = 2; it <= 50; ++it) {
        float tn = (1.0f + sqrtf(1.0f + 4.0f * t * t)) / 2.0f;
        float m = (t - 1.0f) / tn;
        t = tn;
        k_fista<<<dim3(8, 128), 256>>>(m, it & 1);
    }

    k_topk<<<2048, 256>>>();
    k_ids<<<16384, 256>>>(out);
    k_recon<<<128, 256>>>(X, out);
    k_scalars<<<1, 256>>>(out);
}

// round 17
// speedup vs baseline: 1.0013x; 1.0013x over previous
#include <cuda_runtime.h>
#include <cstdint>
#include <cstddef>
#include <math.h>

#define KN 1024       // N_EMBED (atoms)
#define DD 128        // DIM
#define NN 16384      // number of patches (16*32*32)
#define HW 1024       // 32*32

// output flat offsets (tuple flatten order of the reference return)
#define OFF_QD1    2097152
#define OFF_QD2    2097153
#define OFF_IDS    2097154
#define OFF_NSTEPS 18874370
#define OFF_MEAND  18874371
#define OFF_MEANZ  18874372
#define OFF_NORMZ  18874373
#define OFF_TOPP   18874374
#define OFF_NZEROS 18874375

// ---------------- device scratch (allocation-free rule: __device__ globals) ----------
__device__ __align__(16) float d_Dt[KN * DD];
__device__ __align__(16) float d_G[KN * KN];
__device__ __align__(16) float d_DtX[KN * NN];
__device__ __align__(16) float d_Z[KN * NN];
__device__ __align__(16) float d_Y0[KN * NN];
__device__ __align__(16) float d_Y1[KN * NN];
__device__ float d_v[KN];
__device__ float d_w[KN];
__device__ float d_scal[4];              // [0]=step, [1]=thr
__device__ float d_meanD_part[KN];
__device__ float d_sumabs_part[2048];
__device__ float d_qd_part[128];
__device__ int   d_hist[16];

// ---------------- packed f32x2 helpers (Blackwell base-ISA; NOT tcgen05) ------------
// Lane-wise IEEE fp32 RN fma: bitwise identical to the scalar FFMA chain.
__device__ __forceinline__ unsigned long long pack_ff(float x, float y) {
    unsigned long long d;
    asm("mov.b64 %0, {%1, %2};" : "=l"(d)
        : "r"(__float_as_uint(x)), "r"(__float_as_uint(y)));
    return d;
}
__device__ __forceinline__ void fma_f32x2(unsigned long long& c,
                                          unsigned long long a,
                                          unsigned long long b) {
    asm("fma.rn.f32x2 %0, %1, %2, %3;" : "=l"(c) : "l"(a), "l"(b), "l"(c));
}
__device__ __forceinline__ void unpack_ff(float& x, float& y, unsigned long long d) {
    uint32_t lo, hi;
    asm("mov.b64 {%0, %1}, %2;" : "=r"(lo), "=r"(hi) : "l"(d));
    x = __uint_as_float(lo);
    y = __uint_as_float(hi);
}

// ---------------- tiny init ----------------
__global__ void k_init() {
    if (threadIdx.x < 16) d_hist[threadIdx.x] = 0;
}

// ---------------- normalize dictionary columns; build Dt; per-column |.| sums -------
__global__ void k_normalize(const float* __restrict__ D) {
    int k = blockIdx.x;
    int c = threadIdx.x;
    float v = D[c * KN + k];
    __shared__ float red[128];
    __shared__ float nrm;
    red[c] = v * v;
    __syncthreads();
    for (int s = 64; s; s >>= 1) { if (c < s) red[c] += red[c + s]; __syncthreads(); }
    if (c == 0) nrm = sqrtf(red[0]);
    __syncthreads();
    float o = v / nrm;
    d_Dt[k * DD + c] = o;
    red[c] = fabsf(o);
    __syncthreads();
    for (int s = 64; s; s >>= 1) { if (c < s) red[c] += red[c + s]; __syncthreads(); }
    if (c == 0) d_meanD_part[k] = red[0];
}

// ---------------- Gram matrix G = Dt * Dt^T ----------------------
__global__ __launch_bounds__(256) void k_gram() {
    __shared__ float Ai[32][128];
    __shared__ float Aj[32][128];
    int i0 = blockIdx.y * 32, j0 = blockIdx.x * 32;
    int tid = threadIdx.x;
    #pragma unroll
    for (int l = 0; l < 4; l++) {
        int id = tid + l * 256;
        int r = id >> 5, c4 = id & 31;
        *(float4*)&Ai[r][c4 * 4] = *(const float4*)&d_Dt[(i0 + r) * DD + c4 * 4];
        *(float4*)&Aj[r][c4 * 4] = *(const float4*)&d_Dt[(j0 + r) * DD + c4 * 4];
    }
    __syncthreads();
    int tx = tid & 15, ty = tid >> 4;
    float a00 = 0.f, a01 = 0.f, a10 = 0.f, a11 = 0.f;
    #pragma unroll 4
    for (int c = 0; c < 128; c++) {
        float x0 = Ai[ty * 2 + 0][c], x1 = Ai[ty * 2 + 1][c];
        float y0 = Aj[tx * 2 + 0][c], y1 = Aj[tx * 2 + 1][c];
        a00 += x0 * y0; a01 += x0 * y1; a10 += x1 * y0; a11 += x1 * y1;
    }
    d_G[(i0 + ty * 2 + 0) * KN + j0 + tx * 2 + 0] = a00;
    d_G[(i0 + ty * 2 + 0) * KN + j0 + tx * 2 + 1] = a01;
    d_G[(i0 + ty * 2 + 1) * KN + j0 + tx * 2 + 0] = a10;
    d_G[(i0 + ty * 2 + 1) * KN + j0 + tx * 2 + 1] = a11;
}

// ---------------- power iteration ----------------
__global__ void k_pitinit() {
    for (int i = threadIdx.x; i < KN; i += blockDim.x) d_v[i] = 0.03125f;
}
__global__ void k_matvec() {
    int row = blockIdx.x;
    int t = threadIdx.x;
    const float* g = &d_G[row * KN];
    float s = 0.f;
    for (int j = t; j < KN; j += 128) s += g[j] * d_v[j];
    __shared__ float red[128];
    red[t] = s; __syncthreads();
    for (int k2 = 64; k2; k2 >>= 1) { if (t < k2) red[t] += red[t + k2]; __syncthreads(); }
    if (t == 0) d_w[row] = red[0];
}
__global__ void k_pitnorm() {
    int t = threadIdx.x;
    float s = 0.f;
    for (int i = t; i < KN; i += 256) { float w = d_w[i]; s += w * w; }
    __shared__ float red[256];
    __shared__ float nrm;
    red[t] = s; __syncthreads();
    for (int k2 = 128; k2; k2 >>= 1) { if (t < k2) red[t] += red[t + k2]; __syncthreads(); }
    if (t == 0) nrm = sqrtf(red[0]) + 1e-12f;
    __syncthreads();
    for (int i = t; i < KN; i += 256) d_v[i] = d_w[i] / nrm;
}
__global__ void k_pitfinal() {
    int t = threadIdx.x;
    float s = 0.f;
    for (int i = t; i < KN; i += 256) s += d_v[i] * d_w[i];
    __shared__ float red[256];
    red[t] = s; __syncthreads();
    for (int k2 = 128; k2; k2 >>= 1) { if (t < k2) red[t] += red[t + k2]; __syncthreads(); }
    if (t == 0) {
        float step = 1.0f / red[0];
        d_scal[0] = step;
        d_scal[1] = 0.1f * step;
    }
}

// ---------------- DtX = Dt (1024x128) @ X (128x16384) ------------------------------
__global__ __launch_bounds__(256) void k_dtx(const float* __restrict__ X) {
    __shared__ float As[16][128];
    __shared__ float Bs[16][128];
    int tid = threadIdx.x;
    int k0 = blockIdx.x * 128;
    int n0 = blockIdx.y * 128;
    int b = n0 >> 10, hw0 = n0 & 1023;
    const float* Xb = X + b * (DD * HW) + hw0;
    int tx = tid & 15, ty = tid >> 4;
    float acc[8][8];
    #pragma unroll
    for (int i = 0; i < 8; i++)
        #pragma unroll
        for (int j = 0; j < 8; j++) acc[i][j] = 0.f;
    for (int c0 = 0; c0 < DD; c0 += 16) {
        #pragma unroll
        for (int l = 0; l < 2; l++) {
            int id = tid + l * 256;
            int r = id >> 2, q = id & 3;
            float4 av = *(const float4*)&d_Dt[(k0 + r) * DD + c0 + q * 4];
            As[q * 4 + 0][r] = av.x; As[q * 4 + 1][r] = av.y;
            As[q * 4 + 2][r] = av.z; As[q * 4 + 3][r] = av.w;
            int br = id >> 5, bc = id & 31;
            float4 bv = *(const float4*)&Xb[(c0 + br) * HW + bc * 4];
            *(float4*)&Bs[br][bc * 4] = bv;
        }
        __syncthreads();
        #pragma unroll
        for (int kk = 0; kk < 16; kk++) {
            float a[8], bb[8];
            #pragma unroll
            for (int i = 0; i < 8; i++) a[i] = As[kk][ty * 8 + i];
            #pragma unroll
            for (int j = 0; j < 8; j++) bb[j] = Bs[kk][tx * 8 + j];
            #pragma unroll
            for (int i = 0; i < 8; i++)
                #pragma unroll
                for (int j = 0; j < 8; j++) acc[i][j] += a[i] * bb[j];
        }
        __syncthreads();
    }
    #pragma unroll
    for (int i = 0; i < 8; i++) {
        int k = k0 + ty * 8 + i;
        #pragma unroll
        for (int j = 0; j < 8; j++)
            d_DtX[k * NN + n0 + tx * 8 + j] = acc[i][j];
    }
}

// ---------------- FISTA iteration 1 (y0 = 0) ----------------
__global__ void k_first() {
    float step = d_scal[0], thr = d_scal[1];
    for (int i = blockIdx.x * blockDim.x + threadIdx.x; i < KN * NN; i += gridDim.x * blockDim.x) {
        float v = step * d_DtX[i];
        float a = fabsf(v) - thr;
        float z = (a > 0.f) ? copysignf(a, v) : 0.f;
        d_Z[i] = z;
        d_Y0[i] = z;   // momentum for iter 1 is 0 -> y2 = z1
    }
}

// ---------------- main FISTA GEMM: packed-f32x2 pipelined + fused prox/momentum -----
// fma.rn.f32x2 is lane-wise IEEE fp32 RN -> the per-element fma chain (kk ascending)
// is BITWISE IDENTICAL to the scalar FFMA version that passed at 1.524465e-07.
// 2x fp32 issue throughput (FFMA2 rt=1 FMA-slot per lane-pair vs FFMA-3reg rt=2).
__global__ __launch_bounds__(256, 2) void k_fista(float m, int ping) {
    const float* __restrict__ Yin = ping ? d_Y1 : d_Y0;
    float* __restrict__ Yout      = ping ? d_Y0 : d_Y1;
    __shared__ float As[2][16][128];
    __shared__ float Bs[2][16][128];
    int tid = threadIdx.x;
    int k0 = blockIdx.x * 128;   // x fast: 8 k-tiles share the Y n-tile via L2
    int n0 = blockIdx.y * 128;
    int tx = tid & 15, ty = tid >> 4;
    int ar = tid >> 2, aq = tid & 3;     // A ldg coords (rows ar, ar+64)
    int br = tid >> 5, bc = tid & 31;    // B cp.async coords (rows br, br+8)

    uint32_t bsBase;
    asm("{ .reg .u64 t; cvta.to.shared.u64 t, %1; cvt.u32.u64 %0, t; }"
        : "=r"(bsBase) : "l"(&Bs[0][0][0]));

    unsigned long long acc2[8][4];       // [i][j2]: cols {2*j2, 2*j2+1} of the 8-wide j
    #pragma unroll
    for (int i = 0; i < 8; i++)
        #pragma unroll
        for (int j2 = 0; j2 < 4; j2++) acc2[i][j2] = 0ull;

    // prologue: stage chunk 0
    float4 avA0 = *(const float4*)&d_G[(k0 + ar) * KN + aq * 4];
    float4 avA1 = *(const float4*)&d_G[(k0 + ar + 64) * KN + aq * 4];
    {
        const float* s0 = &Yin[br * NN + n0 + bc * 4];
        const float* s1 = &Yin[(br + 8) * NN + n0 + bc * 4];
        uint32_t d0 = bsBase + (uint32_t)((br * 128 + bc * 4) * 4);
        uint32_t d1 = bsBase + (uint32_t)(((br + 8) * 128 + bc * 4) * 4);
        asm volatile("cp.async.ca.shared.global [%0], [%1], 16;" :: "r"(d0), "l"(s0));
        asm volatile("cp.async.ca.shared.global [%0], [%1], 16;" :: "r"(d1), "l"(s1));
        asm volatile("cp.async.commit_group;" ::: "memory");
    }

    for (int c = 0; c < 64; c++) {
        int cur = c & 1;
        // transpose-store staged A chunk c
        As[cur][aq * 4 + 0][ar] = avA0.x;
        As[cur][aq * 4 + 1][ar] = avA0.y;
        As[cur][aq * 4 + 2][ar] = avA0.z;
        As[cur][aq * 4 + 3][ar] = avA0.w;
        As[cur][aq * 4 + 0][ar + 64] = avA1.x;
        As[cur][aq * 4 + 1][ar + 64] = avA1.y;
        As[cur][aq * 4 + 2][ar + 64] = avA1.z;
        As[cur][aq * 4 + 3][ar + 64] = avA1.w;
        asm volatile("cp.async.wait_group 0;" ::: "memory");
        __syncthreads();

        if (c < 63) {
            int kc = (c + 1) * 16;
            avA0 = *(const float4*)&d_G[(k0 + ar) * KN + kc + aq * 4];
            avA1 = *(const float4*)&d_G[(k0 + ar + 64) * KN + kc + aq * 4];
            int nxt = cur ^ 1;
            const float* s0 = &Yin[(kc + br) * NN + n0 + bc * 4];
            const float* s1 = &Yin[(kc + br + 8) * NN + n0 + bc * 4];
            uint32_t d0 = bsBase + (uint32_t)((nxt * 2048 + br * 128 + bc * 4) * 4);
            uint32_t d1 = bsBase + (uint32_t)((nxt * 2048 + (br + 8) * 128 + bc * 4) * 4);
            asm volatile("cp.async.ca.shared.global [%0], [%1], 16;" :: "r"(d0), "l"(s0));
            asm volatile("cp.async.ca.shared.global [%0], [%1], 16;" :: "r"(d1), "l"(s1));
            asm volatile("cp.async.commit_group;" ::: "memory");
        }

        #pragma unroll
        for (int kk = 0; kk < 16; kk++) {
            unsigned long long b2[4];
            #pragma unroll
            for (int j2 = 0; j2 < 4; j2++)
                b2[j2] = *(const unsigned long long*)&Bs[cur][kk][tx * 8 + j2 * 2];
            #pragma unroll
            for (int i = 0; i < 8; i++) {
                float av = As[cur][kk][ty * 8 + i];
                unsigned long long a2 = pack_ff(av, av);
                #pragma unroll
                for (int j2 = 0; j2 < 4; j2++)
                    fma_f32x2(acc2[i][j2], a2, b2[j2]);
            }
        }
        // no trailing barrier: buffers alternate; the one sync above suffices
    }

    float step = d_scal[0], thr = d_scal[1];
    #pragma unroll
    for (int i = 0; i < 8; i++) {
        int k = k0 + ty * 8 + i;
        #pragma unroll
        for (int j2 = 0; j2 < 4; j2++) {
            float g0, g1;
            unpack_ff(g0, g1, acc2[i][j2]);
            #pragma unroll
            for (int h = 0; h < 2; h++) {
                float g = h ? g1 : g0;
                int n = n0 + tx * 8 + j2 * 2 + h;
                int idx = k * NN + n;
                float yv = Yin[idx];
                float dx = d_DtX[idx];
                float zp = d_Z[idx];
                float v = yv - step * (g - dx);
                float a = fabsf(v) - thr;
                float zn = (a > 0.f) ? copysignf(a, v) : 0.f;
                d_Z[idx] = zn;
                Yout[idx] = zn + m * (zn - zp);
            }
        }
    }
}

// ---------------- top-10 per column + 8-bit quantization + stats --------------------
__global__ __launch_bounds__(256) void k_topk() {
    __shared__ float sm[8 * 1025];
    __shared__ float wsum[8];
    int n0 = blockIdx.x * 8;
    int tid = threadIdx.x;
    for (int idx = tid; idx < 8 * 1024; idx += 256) {
        int k = idx >> 3, c = idx & 7;
        sm[c * 1025 + k] = d_Z[k * NN + n0 + c];
    }
    __syncthreads();
    int warp = tid >> 5, lane = tid & 31;
    float* col = &sm[warp * 1025];
    unsigned mask = 0;
    for (int r = 0; r < 10; r++) {
        float best = -1.0f; int bk = 1 << 30;
        #pragma unroll
        for (int i = 0; i < 32; i++) {
            if (!((mask >> i) & 1u)) {
                float v = fabsf(col[i * 32 + lane]);
                if (v > best) { best = v; bk = i * 32 + lane; }
            }
        }
        #pragma unroll
        for (int off = 16; off; off >>= 1) {
            float ov = __shfl_xor_sync(0xffffffffu, best, off);
            int ok = __shfl_xor_sync(0xffffffffu, bk, off);
            if (ov > best || (ov == best && ok < bk)) { best = ov; bk = ok; }
        }
        if (lane == (bk & 31)) mask |= 1u << (bk >> 5);
    }
    float sa = 0.f; int nz = 0;
    #pragma unroll
    for (int i = 0; i < 32; i++) {
        float z = col[i * 32 + lane];
        float q = 0.f;
        if ((mask >> i) & 1u) {
            float zc = fminf(fmaxf(z, -0.55f), 0.55f);
            float u = (zc - (-0.55f)) / (0.55f - (-0.55f));
            u = rintf(u * 256.0f) * 0.00390625f;
            q = u * (0.55f - (-0.55f)) + (-0.55f);
        }
        col[i * 32 + lane] = q;
        sa += fabsf(q);
        nz += (q != 0.f) ? 1 : 0;
    }
    #pragma unroll
    for (int off = 16; off; off >>= 1) {
        sa += __shfl_xor_sync(0xffffffffu, sa, off);
        nz += __shfl_xor_sync(0xffffffffu, nz, off);
    }
    if (lane == 0) { atomicAdd(&d_hist[nz], 1); wsum[warp] = sa; }
    __syncthreads();
    if (tid == 0) {
        float s = 0.f;
        for (int w = 0; w < 8; w++) s += wsum[w];
        d_sumabs_part[blockIdx.x] = s;
    }
    for (int idx = tid; idx < 8 * 1024; idx += 256) {
        int k = idx >> 3, c = idx & 7;
        d_Z[k * NN + n0 + c] = sm[c * 1025 + k];
    }
}

// ---------------- ids output (out+OFF_IDS only 8B aligned -> float2) ----------------
__global__ void k_ids(float* __restrict__ out) {
    int bk = blockIdx.x;
    int k = bk & 1023, b = bk >> 10;
    const float2* src = (const float2*)&d_Z[k * NN + b * HW];
    float2* dst = (float2*)(out + OFF_IDS + (size_t)b * (KN * HW) + (size_t)k * HW);
    int t = threadIdx.x;
    dst[t] = src[t];
    dst[t + 256] = src[t + 256];
}

// ---------------- reconstruction + straight-through + qd ----------------------------
__global__ __launch_bounds__(256) void k_recon(const float* __restrict__ X, float* __restrict__ out) {
    __shared__ float As[16][128];
    __shared__ float Bs[16][128];
    int tid = threadIdx.x;
    int n0 = blockIdx.x * 128;
    int tx = tid & 15, ty = tid >> 4;
    float acc[8][8];
    #pragma unroll
    for (int i = 0; i < 8; i++)
        #pragma unroll
        for (int j = 0; j < 8; j++) acc[i][j] = 0.f;
    for (int k0 = 0; k0 < KN; k0 += 16) {
        #pragma unroll
        for (int l = 0; l < 2; l++) {
            int id = tid + l * 256;
            int r = id >> 5, c4 = id & 31;
            *(float4*)&As[r][c4 * 4] = *(const float4*)&d_Dt[(k0 + r) * DD + c4 * 4];
            *(float4*)&Bs[r][c4 * 4] = *(const float4*)&d_Z[(k0 + r) * NN + n0 + c4 * 4];
        }
        __syncthreads();
        #pragma unroll
        for (int kk = 0; kk < 16; kk++) {
            float a[8], bb[8];
            #pragma unroll
            for (int i = 0; i < 8; i++) a[i] = As[kk][ty * 8 + i];
            #pragma unroll
            for (int j = 0; j < 8; j++) bb[j] = Bs[kk][tx * 8 + j];
            #pragma unroll
            for (int i = 0; i < 8; i++)
                #pragma unroll
                for (int j = 0; j < 8; j++) acc[i][j] += a[i] * bb[j];
        }
        __syncthreads();
    }
    int b = n0 >> 10, hw0 = n0 & 1023;
    float sq = 0.f;
    #pragma unroll
    for (int i = 0; i < 8; i++) {
        int c = ty * 8 + i;
        #pragma unroll
        for (int j = 0; j < 8; j++) {
            int hw = hw0 + tx * 8 + j;
            int gi = b * (DD * HW) + c * HW + hw;
            float x = X[gi];
            float d = acc[i][j] - x;
            sq += d * d;
            out[gi] = x + d;
        }
    }
    __shared__ float red[256];
    red[tid] = sq; __syncthreads();
    for (int k2 = 128; k2; k2 >>= 1) { if (tid < k2) red[tid] += red[tid + k2]; __syncthreads(); }
    if (tid == 0) d_qd_part[blockIdx.x] = red[0];
}

// ---------------- final scalars ----------------
__global__ void k_scalars(float* __restrict__ out) {
    __shared__ float red[256];
    int t = threadIdx.x;
    float s = (t < 128) ? d_qd_part[t] : 0.f;
    red[t] = s; __syncthreads();
    for (int k2 = 128; k2; k2 >>= 1) { if (t < k2) red[t] += red[t + k2]; __syncthreads(); }
    if (t == 0) { float qd = red[0] / 2097152.0f; out[OFF_QD1] = qd; out[OFF_QD2] = qd; }
    __syncthreads();
    s = 0.f;
    for (int i = t; i < KN; i += 256) s += d_meanD_part[i];
    red[t] = s; __syncthreads();
    for (int k2 = 128; k2; k2 >>= 1) { if (t < k2) red[t] += red[t + k2]; __syncthreads(); }
    if (t == 0) out[OFF_MEAND] = red[0] / 131072.0f;
    __syncthreads();
    s = 0.f;
    for (int i = t; i < 2048; i += 256) s += d_sumabs_part[i];
    red[t] = s; __syncthreads();
    for (int k2 = 128; k2; k2 >>= 1) { if (t < k2) red[t] += red[t + k2]; __syncthreads(); }
    if (t == 0) out[OFF_MEANZ] = red[0] / 16777216.0f;
    if (t == 0) {
        out[OFF_NSTEPS] = 50.0f;
        int cum = 0, perc = 0, found = 0;
        for (int v = 10; v >= 0; v--) {
            cum += d_hist[v];
            if (!found && cum >= 163) { perc = v; found = 1; }
        }
        float sv = 0.f;
        for (int v = 1; v <= 10; v++) sv += (float)v * (float)d_hist[v];
        out[OFF_NORMZ]  = sv / 16384.0f;
        out[OFF_TOPP]   = (float)perc;
        out[OFF_NZEROS] = (float)d_hist[0];
    }
}

// ---------------- host driver ----------------
extern "C" void kernel_launch(void* const* d_in, const int* in_sizes, int n_in,
                              void* d_out, int out_size) {
    (void)n_in; (void)out_size;
    const float* a0 = (const float*)d_in[0];
    const float* a1 = (const float*)d_in[1];
    const float* X; const float* Ddict;
    if (in_sizes[0] == KN * DD) { Ddict = a0; X = a1; }
    else                        { X = a0;     Ddict = a1; }
    float* out = (float*)d_out;

    k_init<<<1, 32>>>();
    k_normalize<<<KN, 128>>>(Ddict);
    k_gram<<<dim3(32, 32), 256>>>();
    k_pitinit<<<1, 256>>>();
    for (int i = 0; i < 20; i++) {
        k_matvec<<<KN, 128>>>();
        k_pitnorm<<<1, 256>>>();
    }
    k_matvec<<<KN, 128>>>();
    k_pitfinal<<<1, 256>>>();

    k_dtx<<<dim3(8, 128), 256>>>(X);
    k_first<<<4096, 256>>>();

    // fp32 Nesterov recurrence, mirroring the JAX op order
    float t = 1.0f;
    {   // iteration 1 (consumed by k_first, momentum 0)
        float tn = (1.0f + sqrtf(1.0f + 4.0f * t * t)) / 2.0f;
        t = tn;
    }
    for (int it = 2; it <= 50; ++it) {
        float tn = (1.0f + sqrtf(1.0f + 4.0f * t * t)) / 2.0f;
        float m = (t - 1.0f) / tn;
        t = tn;
        k_fista<<<dim3(8, 128), 256>>>(m, it & 1);
    }

    k_topk<<<2048, 256>>>();
    k_ids<<<16384, 256>>>(out);
    k_recon<<<128, 256>>>(X, out);
    k_scalars<<<1, 256>>>(out);
}